// round 2
// baseline (speedup 1.0000x reference)
#include <cuda_runtime.h>
#include <cuda_bf16.h>
#include <cstdint>

// Problem: B=32, Cin=Cout=128, H=W=128, 3x3 conv (zero pad 1) + bias
//          minus THETA * central-difference Laplacian (edge-replicate) of channel-sum.
// Inputs (metadata order): x [32,128,128,128] f32, W [128,128,3,3] f32, b [128] f32.
// Output: [32,128,128,128] f32.

#define B_     32
#define C_     128
#define HW_    128
#define HWSQ   (HW_*HW_)          // 16384
#define THETA  0.7f

// ---- scratch (device globals: allocation-free per harness rules) ----
__device__ float g_s [B_*HWSQ];        // channel sum      (2 MB)
__device__ float g_t [B_*HWSQ];        // -theta * laplacian (2 MB)
__device__ float g_wt[C_*9*C_];        // W transposed to [ci][tap][co] (576 KB)

// ============================================================
// Kernel 0: transpose weights [co][ci][t] -> [ci][t][co]
// ============================================================
__global__ void wt_kernel(const float* __restrict__ W) {
    int i = blockIdx.x * 256 + threadIdx.x;           // over 128*128*9 = 147456
    if (i < C_*C_*9) {
        int co  = i / (C_*9);
        int rem = i - co * (C_*9);
        int ci  = rem / 9;
        int t   = rem - ci * 9;
        g_wt[ci * (9*C_) + t * C_ + co] = W[i];
    }
}

// ============================================================
// Kernel 1: s[b,h,w] = sum_c x[b,c,h,w]
// ============================================================
__global__ void sum_kernel(const float* __restrict__ x) {
    int idx = blockIdx.x * 256 + threadIdx.x;         // over B*H*W = 524288
    int b   = idx >> 14;
    int hw  = idx & (HWSQ - 1);
    const float* xp = x + (size_t)b * C_ * HWSQ + hw;
    float acc = 0.f;
    #pragma unroll 8
    for (int c = 0; c < C_; c++) acc += xp[(size_t)c * HWSQ];
    g_s[idx] = acc;
}

// ============================================================
// Kernel 2: t = -theta * (up+down+left+right - 4*center), replicate edges
// ============================================================
__global__ void lap_kernel() {
    int idx = blockIdx.x * 256 + threadIdx.x;
    int b   = idx >> 14;
    int hw  = idx & (HWSQ - 1);
    int h   = hw >> 7;
    int w   = hw & 127;
    const float* sb = g_s + ((size_t)b << 14);
    float c  = sb[hw];
    float up = sb[(h > 0   ? h-1 : 0  ) * HW_ + w];
    float dn = sb[(h < 127 ? h+1 : 127) * HW_ + w];
    float lf = sb[h * HW_ + (w > 0   ? w-1 : 0  )];
    float rt = sb[h * HW_ + (w < 127 ? w+1 : 127)];
    g_t[idx] = -THETA * (up + dn + lf + rt - 4.f * c);
}

// ============================================================
// Kernel 3: main conv. CTA = 128 couts x (8 rows x 16 cols) pixels.
// 256 threads; per-thread register tile 8 couts x 8 pixels (one row, 8 cols).
// K-loop over cin in chunks of 8; 9 taps unrolled.
// ============================================================
#define TH 8
#define TW 16
#define CK 8
#define XSTR 19          // row stride (odd) -> 16 pixel-lane banks all distinct

__global__ void __launch_bounds__(256, 2)
conv_kernel(const float* __restrict__ x, const float* __restrict__ bias,
            float* __restrict__ out) {
    __shared__ float s_x[CK][TH + 2][XSTR];   //  6.08 KB
    __shared__ float s_w[CK][9][C_];          // 36.86 KB

    const int b   = blockIdx.z;
    const int h0  = blockIdx.y * TH;
    const int w0  = blockIdx.x * TW;

    const int tid = threadIdx.x;
    const int cg  = tid >> 4;                 // 0..15 : cout group
    const int pg  = tid & 15;                 // 0..15 : pixel group
    const int r   = pg >> 1;                  // 0..7  : row in tile
    const int c0  = (pg & 1) * 8;             // 0 / 8 : col offset
    const int co0 = cg * 8;

    float acc[8][8];
    #pragma unroll
    for (int a = 0; a < 8; a++)
        #pragma unroll
        for (int j = 0; j < 8; j++) acc[a][j] = 0.f;

    const float* xb = x + (size_t)b * C_ * HWSQ;

    for (int cc = 0; cc < C_; cc += CK) {
        // ---- load x tile (10 x 18 x CK), zero pad outside image ----
        for (int i = tid; i < CK * (TH+2) * (TW+2); i += 256) {
            int ci  = i / ((TH+2) * (TW+2));
            int rem = i - ci * ((TH+2) * (TW+2));
            int rr  = rem / (TW+2);
            int ccx = rem - rr * (TW+2);
            int h = h0 + rr - 1;
            int w = w0 + ccx - 1;
            float v = 0.f;
            if ((unsigned)h < (unsigned)HW_ && (unsigned)w < (unsigned)HW_)
                v = xb[(size_t)(cc + ci) * HWSQ + h * HW_ + w];
            s_x[ci][rr][ccx] = v;
        }
        // ---- load weight chunk [ci][t][co], fully coalesced from g_wt ----
        {
            float* sw = &s_w[0][0][0];
            const float* gw = g_wt + cc * (9 * C_);
            for (int i = tid; i < CK * 9 * C_; i += 256)
                sw[i] = gw[i];
        }
        __syncthreads();

        #pragma unroll 2
        for (int ci = 0; ci < CK; ci++) {
            const float* xp = &s_x[ci][r][c0];
            const float* wp = &s_w[ci][0][co0];
            #pragma unroll
            for (int t9 = 0; t9 < 9; t9++) {
                const int kh = t9 / 3, kw = t9 % 3;
                float xv[8], wv[8];
                #pragma unroll
                for (int j = 0; j < 8; j++) xv[j] = xp[kh * XSTR + kw + j];
                #pragma unroll
                for (int a = 0; a < 8; a++) wv[a] = wp[t9 * C_ + a];
                #pragma unroll
                for (int a = 0; a < 8; a++)
                    #pragma unroll
                    for (int j = 0; j < 8; j++)
                        acc[a][j] += wv[a] * xv[j];
            }
        }
        __syncthreads();
    }

    // ---- epilogue: + bias[co] + t[b,h,w] ; float4 stores ----
    const int h  = h0 + r;
    const int wc = w0 + c0;
    float tv[8];
    const float* tp = g_t + ((size_t)b << 14) + h * HW_ + wc;
    #pragma unroll
    for (int j = 0; j < 8; j++) tv[j] = tp[j];

    #pragma unroll
    for (int a = 0; a < 8; a++) {
        float bv = bias[co0 + a];
        float4 o0, o1;
        o0.x = acc[a][0] + bv + tv[0];
        o0.y = acc[a][1] + bv + tv[1];
        o0.z = acc[a][2] + bv + tv[2];
        o0.w = acc[a][3] + bv + tv[3];
        o1.x = acc[a][4] + bv + tv[4];
        o1.y = acc[a][5] + bv + tv[5];
        o1.z = acc[a][6] + bv + tv[6];
        o1.w = acc[a][7] + bv + tv[7];
        float* op = out + (((size_t)b * C_ + (co0 + a)) << 14) + h * HW_ + wc;
        reinterpret_cast<float4*>(op)[0] = o0;
        reinterpret_cast<float4*>(op)[1] = o1;
    }
}

// ============================================================
extern "C" void kernel_launch(void* const* d_in, const int* in_sizes, int n_in,
                              void* d_out, int out_size) {
    const float* x    = (const float*)d_in[0];
    const float* W    = (const float*)d_in[1];
    const float* bias = (const float*)d_in[2];
    float* out        = (float*)d_out;

    wt_kernel <<<(C_*C_*9 + 255) / 256, 256>>>(W);
    sum_kernel<<<(B_*HWSQ) / 256, 256>>>(x);
    lap_kernel<<<(B_*HWSQ) / 256, 256>>>();

    dim3 grid(HW_ / TW, HW_ / TH, B_);   // (8, 16, 32)
    conv_kernel<<<grid, 256>>>(x, bias, out);
}